// round 10
// baseline (speedup 1.0000x reference)
#include <cuda_runtime.h>
#include <cuda_fp16.h>
#include <math.h>
#include <stdint.h>

#define BATCH   131072
#define HID     512
#define LDIM    8
#define NTH     45
#define NSTEPS  20

// ============================================================================
// Baseline-PTX tensor helpers (compute_103-safe: ldmatrix + mma.sync only)
// ============================================================================
__device__ __forceinline__ uint32_t smem_u32(const void* p) {
    uint32_t a;
    asm("{ .reg .u64 t; cvta.to.shared.u64 t, %1; cvt.u32.u64 %0, t; }"
        : "=r"(a) : "l"(p));
    return a;
}

#define LDSM4(r0, r1, r2, r3, addr) \
    asm volatile("ldmatrix.sync.aligned.m8n8.x4.shared.b16 {%0,%1,%2,%3}, [%4];" \
        : "=r"(r0), "=r"(r1), "=r"(r2), "=r"(r3) : "r"(addr))

// fp16 inputs, fp32 accumulate
#define MMA16816(d, a, b0, b1) \
    asm volatile("mma.sync.aligned.m16n8k16.row.col.f32.f16.f16.f32 " \
        "{%0,%1,%2,%3},{%4,%5,%6,%7},{%8,%9},{%0,%1,%2,%3};" \
        : "+f"((d)[0]), "+f"((d)[1]), "+f"((d)[2]), "+f"((d)[3]) \
        : "r"((a)[0]), "r"((a)[1]), "r"((a)[2]), "r"((a)[3]), \
          "r"(b0), "r"(b1))

__device__ __forceinline__ void cp16(uint32_t dst, const void* src) {
    asm volatile("cp.async.cg.shared.global [%0], [%1], 16;"
        :: "r"(dst), "l"(src));
}
#define CP_COMMIT() asm volatile("cp.async.commit_group;" ::: "memory")
#define CP_WAIT(n)  asm volatile("cp.async.wait_group %0;" :: "n"(n) : "memory")

__device__ __forceinline__ uint32_t pack_h2(float a, float b) {
    __half2 t = __floats2half2_rn(a, b);
    return reinterpret_cast<uint32_t&>(t);
}

// ============================================================================
// Scratch: activations as row-major fp16 hi/lo pairs (exact 2-term split).
// Weights: single fp16, pre-transposed WT[n][kpad], zero-pad k>=K.
// ============================================================================
__device__ __half g_hA_hi[BATCH * HID], g_hA_lo[BATCH * HID];
__device__ __half g_hB_hi[BATCH * HID], g_hB_lo[BATCH * HID];
__device__ __half g_x_hi[BATCH * 64],   g_x_lo[BATCH * 64];
__device__ __half g_z_hi[BATCH * 32],   g_z_lo[BATCH * 32];   // zt pad 32
__device__ float  g_z0[BATCH * LDIM];

__device__ __half g_w1[512 * 64];     // enc_W1  KPAD=64
__device__ __half g_w2[512 * 512];    // enc_W2  KPAD=512
__device__ __half g_d1[512 * 32];     // dec_W1  K=8 -> KPAD=32
__device__ __half g_d2[512 * 512];    // dec_W2  KPAD=512
__device__ __half g_d3[64 * 512];     // dec_W3  KPAD=512

// ============================================================================
// prep: all five weights in ONE launch (transpose + fp16 round + zero-pad)
// ============================================================================
#define SEG0 32768            // w1  (K=64,  N=512, KPAD=64)
#define SEG1 (SEG0 + 262144)  // w2  (K=512, N=512, KPAD=512)
#define SEG2 (SEG1 + 16384)   // d1  (K=8,   N=512, KPAD=32)
#define SEG3 (SEG2 + 262144)  // d2  (K=512, N=512, KPAD=512)
#define SEG4 (SEG3 + 32768)   // d3  (K=512, N=64,  KPAD=512)

__global__ void prep_all_kernel(const float* __restrict__ eW1,
                                const float* __restrict__ eW2,
                                const float* __restrict__ dW1,
                                const float* __restrict__ dW2,
                                const float* __restrict__ dW3,
                                __half* __restrict__ w1, __half* __restrict__ w2,
                                __half* __restrict__ d1, __half* __restrict__ d2,
                                __half* __restrict__ d3)
{
    int idx = blockIdx.x * 256 + threadIdx.x;
    if (idx >= SEG4) return;
    const float* W; __half* O; int K, N, KPAD, off;
    if (idx < SEG0)      { W = eW1; O = w1; K = 64;  N = 512; KPAD = 64;  off = 0;    }
    else if (idx < SEG1) { W = eW2; O = w2; K = 512; N = 512; KPAD = 512; off = SEG0; }
    else if (idx < SEG2) { W = dW1; O = d1; K = 8;   N = 512; KPAD = 32;  off = SEG1; }
    else if (idx < SEG3) { W = dW2; O = d2; K = 512; N = 512; KPAD = 512; off = SEG2; }
    else                 { W = dW3; O = d3; K = 512; N = 64;  KPAD = 512; off = SEG3; }
    int i = idx - off;
    int n = i / KPAD, k = i % KPAD;
    float v = (k < K) ? W[(size_t)k * N + n] : 0.f;
    O[i] = __float2half_rn(v);
}

__global__ void prep_x_kernel(const float* __restrict__ x0,
                              __half* __restrict__ hi, __half* __restrict__ lo)
{
    size_t idx = (size_t)blockIdx.x * 256 + threadIdx.x;
    float v = x0[idx];
    __half h = __float2half_rn(v);
    hi[idx] = h;
    lo[idx] = __float2half_rn(v - __half2float(h));
}

// ============================================================================
// wide layer: O[B,512] = SiLU(LN(A[B,KPAD] @ W + b)), fp16x2 split (A hi/lo,
// B single fp16). CTA: M=32, N=512 (full row -> fused LN). 256 thr = 8 warps,
// all at warp tile m32 x n64 (warp w owns cols w*64..w*64+63). BK=32,
// 2-stage cp.async double buffer. 2 CTAs/SM (launch_bounds(256,2)) so one
// CTA's barrier/CP_WAIT bubbles are covered by the other CTA's MMA stream.
// smem rows padded to 80B -> conflict-free ldmatrix.
// WRITE_Z: skip activation store; fuse z0 = tanh(h @ W3 + b3)
//          (W3 staged into the dead stage-0 smem after the mainloop).
// ============================================================================
#define LDR 80
#define WST      46080                          // bytes per stage
#define WS_AH(s) ((s) * WST)                    // A hi: 32*80 = 2560
#define WS_AL(s) ((s) * WST + 2560)             // A lo: 2560
#define WS_B(s)  ((s) * WST + 5120)             // B: 512*80 = 40960
#define WS_PAR   92160                          // bias/g/beta 3x2048
#define WS_RED   98304                          // sums/mu/rs 4x128
#define WS_Z     99328                          // 32x8 fp32 = 1024
#define SM_WIDE  100352

template<int KPAD, bool WRITE_Z>
__global__ __launch_bounds__(256, 2)
void wide_mma_kernel(const __half* __restrict__ Ahi,
                     const __half* __restrict__ Alo,
                     const __half* __restrict__ W,
                     const float* __restrict__ bias,
                     const float* __restrict__ gamma,
                     const float* __restrict__ beta,
                     __half* __restrict__ Ohi,
                     __half* __restrict__ Olo,
                     const float* __restrict__ W3,
                     const float* __restrict__ b3,
                     float* __restrict__ z0out)
{
    constexpr int NC = KPAD / 32;
    extern __shared__ char smem[];
    const uint32_t sb = smem_u32(smem);
    const int tid = threadIdx.x, lane = tid & 31, w = tid >> 5;  // 8 warps
    const int nbase = w * 64;
    const int tile = blockIdx.x;                 // 32-row tile

    float* sBias = (float*)(smem + WS_PAR);
    float* sG    = (float*)(smem + WS_PAR + 2048);
    float* sBe   = (float*)(smem + WS_PAR + 4096);
    float* sSum  = (float*)(smem + WS_RED);
    float* sSum2 = (float*)(smem + WS_RED + 128);
    float* sMu   = (float*)(smem + WS_RED + 256);
    float* sRs   = (float*)(smem + WS_RED + 384);
    float* sZ    = (float*)(smem + WS_Z);

    for (int i = tid; i < 512; i += 256) {
        sBias[i] = bias[i]; sG[i] = gamma[i]; sBe[i] = beta[i];
    }
    if (tid < 32) { sSum[tid] = 0.f; sSum2[tid] = 0.f; }
    if (WRITE_Z) sZ[tid] = 0.f;                  // 32*8 = 256 entries

    // chunk loader: B single fp16 (512 rows x 64B), A hi+lo (32 rows x 64B each)
    auto load_chunk = [&](int c, int s) {
        const int kbase = c * 32;
        const uint32_t bB = sb + WS_B(s);
        for (int i = tid; i < 2048; i += 256) {
            const int row = i >> 2, j = i & 3;
            cp16(bB + row * LDR + j * 16,
                 (const char*)W + ((size_t)row * KPAD + kbase) * 2 + j * 16);
        }
        {
            const int row = tid >> 3, q = tid & 7, j = q & 3;   // 32 rows x 8
            const bool hi = q < 4;
            const uint32_t dst = sb + (hi ? WS_AH(s) : WS_AL(s)) + row * LDR + j * 16;
            const char* src = (const char*)(hi ? Ahi : Alo)
                            + (((size_t)tile * 32 + row) * KPAD + kbase) * 2 + j * 16;
            cp16(dst, src);
        }
        CP_COMMIT();
    };

    load_chunk(0, 0);
    if (NC > 1) load_chunk(1, 1); else CP_COMMIT();

    float acc[2][8][4];
#pragma unroll
    for (int i = 0; i < 2; i++)
#pragma unroll
        for (int j = 0; j < 8; j++)
#pragma unroll
            for (int r = 0; r < 4; r++) acc[i][j][r] = 0.f;

    const int arow = ((lane >> 3) & 1) * 8 + (lane & 7);
    const int acol = (lane >> 4) * 8;
    const int brow = ((lane >> 4) & 1) * 8 + (lane & 7);
    const int bcol = ((lane >> 3) & 1) * 8;

#pragma unroll 1
    for (int c = 0; c < NC; c++) {
        if (c + 1 < NC) CP_WAIT(1); else CP_WAIT(0);
        __syncthreads();
        const int sel = c & 1;
        const uint32_t bAh = sb + WS_AH(sel);
        const uint32_t bAl = sb + WS_AL(sel);
        const uint32_t bB  = sb + WS_B(sel);
#pragma unroll
        for (int ks = 0; ks < 32; ks += 16) {
            uint32_t ah[2][4], al[2][4];
#pragma unroll
            for (int mf = 0; mf < 2; mf++) {
                const uint32_t ao = (uint32_t)((mf * 16 + arow) * LDR
                                               + (ks + acol) * 2);
                LDSM4(ah[mf][0], ah[mf][1], ah[mf][2], ah[mf][3], bAh + ao);
                LDSM4(al[mf][0], al[mf][1], al[mf][2], al[mf][3], bAl + ao);
            }
#pragma unroll
            for (int nq = 0; nq < 4; nq++) {
                const uint32_t bo = (uint32_t)((nbase + nq * 16 + brow) * LDR
                                               + (ks + bcol) * 2);
                uint32_t b[4];
                LDSM4(b[0], b[1], b[2], b[3], bB + bo);
#pragma unroll
                for (int mf = 0; mf < 2; mf++) {
                    float* d0 = acc[mf][nq * 2];
                    float* d1 = acc[mf][nq * 2 + 1];
                    MMA16816(d0, ah[mf], b[0], b[1]);
                    MMA16816(d0, al[mf], b[0], b[1]);
                    MMA16816(d1, ah[mf], b[2], b[3]);
                    MMA16816(d1, al[mf], b[2], b[3]);
                }
            }
        }
        __syncthreads();
        if (c + 2 < NC) load_chunk(c + 2, sel);
    }

    // ---------------- epilogue: bias -> LN stats ----------------------------
#pragma unroll
    for (int mf = 0; mf < 2; mf++)
#pragma unroll
        for (int rh = 0; rh < 2; rh++) {
            float s = 0.f, s2 = 0.f;
#pragma unroll
            for (int idx = 0; idx < 8; idx++) {
                const int c0 = nbase + idx * 8 + (lane & 3) * 2;
                float v0 = acc[mf][idx][rh * 2]     + sBias[c0];
                float v1 = acc[mf][idx][rh * 2 + 1] + sBias[c0 + 1];
                acc[mf][idx][rh * 2] = v0; acc[mf][idx][rh * 2 + 1] = v1;
                s += v0 + v1; s2 += v0 * v0 + v1 * v1;
            }
            s  += __shfl_xor_sync(0xffffffffu, s, 1);
            s  += __shfl_xor_sync(0xffffffffu, s, 2);
            s2 += __shfl_xor_sync(0xffffffffu, s2, 1);
            s2 += __shfl_xor_sync(0xffffffffu, s2, 2);
            if ((lane & 3) == 0) {
                const int row = mf * 16 + (lane >> 2) + rh * 8;
                atomicAdd(&sSum[row], s);
                atomicAdd(&sSum2[row], s2);
            }
        }

    // stage-0 smem is dead now (all cp.async drained; last compute used the
    // final stage). Stage W3 there for the fused enc3 GEMM (16KB < WST).
    float* sW3 = (float*)(smem + WS_AH(0));
    if (WRITE_Z) {
        for (int i = tid; i < 512 * 8; i += 256) sW3[i] = W3[i];
    }
    __syncthreads();
    if (tid < 32) {
        const float mu = sSum[tid] * (1.f / 512.f);
        const float var = sSum2[tid] * (1.f / 512.f) - mu * mu;
        sMu[tid] = mu; sRs[tid] = rsqrtf(var + 1e-5f);
    }
    __syncthreads();

    // ---------------- LN + SiLU, store split or fused z = tanh(h@W3+b3) -----
#pragma unroll
    for (int mf = 0; mf < 2; mf++)
#pragma unroll
        for (int rh = 0; rh < 2; rh++) {
            const int row = mf * 16 + (lane >> 2) + rh * 8;
            const float mu = sMu[row], rs = sRs[row];
            float zp[8];
            if (WRITE_Z) {
#pragma unroll
                for (int j = 0; j < 8; j++) zp[j] = 0.f;
            }
            const size_t rowg = (size_t)tile * 32 + row;
#pragma unroll
            for (int idx = 0; idx < 8; idx++) {
                const int c0 = nbase + idx * 8 + (lane & 3) * 2;
                float y0 = (acc[mf][idx][rh * 2]     - mu) * rs * sG[c0]     + sBe[c0];
                float y1 = (acc[mf][idx][rh * 2 + 1] - mu) * rs * sG[c0 + 1] + sBe[c0 + 1];
                y0 = y0 * (1.f / (1.f + __expf(-y0)));
                y1 = y1 * (1.f / (1.f + __expf(-y1)));
                if (WRITE_Z) {
                    const float* w0 = sW3 + c0 * 8;
#pragma unroll
                    for (int j = 0; j < 8; j++) {
                        zp[j] = fmaf(y0, w0[j], zp[j]);
                        zp[j] = fmaf(y1, w0[8 + j], zp[j]);
                    }
                } else {
                    const float h0 = __half2float(__float2half_rn(y0));
                    const float h1 = __half2float(__float2half_rn(y1));
                    *(uint32_t*)(Ohi + rowg * 512 + c0) = pack_h2(h0, h1);
                    *(uint32_t*)(Olo + rowg * 512 + c0) = pack_h2(y0 - h0, y1 - h1);
                }
            }
            if (WRITE_Z) {
#pragma unroll
                for (int j = 0; j < 8; j++) {
                    zp[j] += __shfl_xor_sync(0xffffffffu, zp[j], 1);
                    zp[j] += __shfl_xor_sync(0xffffffffu, zp[j], 2);
                }
                if ((lane & 3) == 0)
#pragma unroll
                    for (int j = 0; j < 8; j++)
                        atomicAdd(&sZ[row * 8 + j], zp[j]);
            }
        }

    if (WRITE_Z) {
        __syncthreads();
        if (tid < 32) {
            const size_t rowg = (size_t)tile * 32 + tid;
#pragma unroll
            for (int j = 0; j < 8; j++)
                z0out[rowg * 8 + j] = tanhf(sZ[tid * 8 + j] + __ldg(b3 + j));
        }
    }
}

// ============================================================================
// out layer: out[B,64] = A[B,512] @ W3 + b3 (fp32 out, no LN).
// CTA: M=128, N=64. 256 thr = 8 warps (4Mx2N), warp m32 x n32. BK=32,
// 2-stage double buffer, 2 CTAs/SM.
// ============================================================================
#define OST      25600
#define OS_AH(s) ((s) * OST)                    // 128*80 = 10240
#define OS_AL(s) ((s) * OST + 10240)
#define OS_B(s)  ((s) * OST + 20480)            // 64*80  = 5120
#define SM_OUT   51200

__global__ __launch_bounds__(256, 2)
void out_mma_kernel(const __half* __restrict__ Ahi,
                    const __half* __restrict__ Alo,
                    const __half* __restrict__ W,
                    const float* __restrict__ bias,
                    float* __restrict__ out)
{
    constexpr int NC = 16;
    extern __shared__ char smem[];
    const uint32_t sb = smem_u32(smem);
    const int tid = threadIdx.x, lane = tid & 31, w = tid >> 5;
    const int warpM = w >> 1, warpN = w & 1;
    const int nbase = warpN * 32;
    const int tile = blockIdx.x;

    auto load_chunk = [&](int c, int s) {
        const int kbase = c * 32;
        {
            const int row = tid >> 2, j = tid & 3;   // 64 rows x 4
            cp16(sb + OS_B(s) + row * LDR + j * 16,
                 (const char*)W + ((size_t)row * 512 + kbase) * 2 + j * 16);
        }
        for (int i = tid; i < 1024; i += 256) {      // 128 rows x (4 hi + 4 lo)
            const int row = i >> 3, q = i & 7, j = q & 3;
            const bool hi = q < 4;
            const uint32_t dst = sb + (hi ? OS_AH(s) : OS_AL(s)) + row * LDR + j * 16;
            const char* src = (const char*)(hi ? Ahi : Alo)
                            + (((size_t)tile * 128 + row) * 512 + kbase) * 2 + j * 16;
            cp16(dst, src);
        }
        CP_COMMIT();
    };

    load_chunk(0, 0);
    load_chunk(1, 1);

    float acc[2][4][4];
#pragma unroll
    for (int i = 0; i < 2; i++)
#pragma unroll
        for (int j = 0; j < 4; j++)
#pragma unroll
            for (int r = 0; r < 4; r++) acc[i][j][r] = 0.f;

    const int arow = ((lane >> 3) & 1) * 8 + (lane & 7);
    const int acol = (lane >> 4) * 8;
    const int brow = ((lane >> 4) & 1) * 8 + (lane & 7);
    const int bcol = ((lane >> 3) & 1) * 8;

#pragma unroll 1
    for (int c = 0; c < NC; c++) {
        if (c + 1 < NC) CP_WAIT(1); else CP_WAIT(0);
        __syncthreads();
        const int sel = c & 1;
        const uint32_t bAh = sb + OS_AH(sel);
        const uint32_t bAl = sb + OS_AL(sel);
        const uint32_t bB  = sb + OS_B(sel);
#pragma unroll
        for (int ks = 0; ks < 32; ks += 16) {
            uint32_t ah[2][4], al[2][4];
#pragma unroll
            for (int mf = 0; mf < 2; mf++) {
                const uint32_t ao = (uint32_t)((warpM * 32 + mf * 16 + arow) * LDR
                                               + (ks + acol) * 2);
                LDSM4(ah[mf][0], ah[mf][1], ah[mf][2], ah[mf][3], bAh + ao);
                LDSM4(al[mf][0], al[mf][1], al[mf][2], al[mf][3], bAl + ao);
            }
#pragma unroll
            for (int nq = 0; nq < 2; nq++) {
                const uint32_t bo = (uint32_t)((nbase + nq * 16 + brow) * LDR
                                               + (ks + bcol) * 2);
                uint32_t b[4];
                LDSM4(b[0], b[1], b[2], b[3], bB + bo);
#pragma unroll
                for (int mf = 0; mf < 2; mf++) {
                    float* d0 = acc[mf][nq * 2];
                    float* d1 = acc[mf][nq * 2 + 1];
                    MMA16816(d0, ah[mf], b[0], b[1]);
                    MMA16816(d0, al[mf], b[0], b[1]);
                    MMA16816(d1, ah[mf], b[2], b[3]);
                    MMA16816(d1, al[mf], b[2], b[3]);
                }
            }
        }
        __syncthreads();
        if (c + 2 < NC) load_chunk(c + 2, sel);
    }

#pragma unroll
    for (int mf = 0; mf < 2; mf++)
#pragma unroll
        for (int rh = 0; rh < 2; rh++) {
            const int row = warpM * 32 + mf * 16 + (lane >> 2) + rh * 8;
            const size_t rowg = (size_t)tile * 128 + row;
#pragma unroll
            for (int idx = 0; idx < 4; idx++) {
                const int c0 = nbase + idx * 8 + (lane & 3) * 2;
                float2 o;
                o.x = acc[mf][idx][rh * 2]     + __ldg(bias + c0);
                o.y = acc[mf][idx][rh * 2 + 1] + __ldg(bias + c0 + 1);
                *(float2*)(out + rowg * 64 + c0) = o;
            }
        }
}

// ============================================================================
// integrator: 20 Euler steps; outputs split fp16 row-major padded to 32 cols
// ============================================================================
__global__ __launch_bounds__(256, 4)
void integrate_kernel(const float* __restrict__ z0,
                      const float* __restrict__ dtv,
                      const float* __restrict__ Xi,
                      __half* __restrict__ Zhi,
                      __half* __restrict__ Zlo)
{
    __shared__ float Xis[NTH * LDIM];
    for (int i = threadIdx.x; i < NTH * LDIM; i += 256) Xis[i] = Xi[i];
    __syncthreads();

    const size_t row = (size_t)blockIdx.x * 256 + threadIdx.x;
    float z[8];
    *(float4*)&z[0] = *(const float4*)(z0 + row * 8);
    *(float4*)&z[4] = *(const float4*)(z0 + row * 8 + 4);
    const float dt = dtv[row] * (1.f / (float)NSTEPS);

#pragma unroll 1
    for (int s = 0; s < NSTEPS; s++) {
        float zd[8];
#pragma unroll
        for (int j = 0; j < 8; j++) zd[j] = Xis[j];
#pragma unroll
        for (int i = 0; i < 8; i++) {
            const float t = z[i];
#pragma unroll
            for (int j = 0; j < 8; j++)
                zd[j] = fmaf(t, Xis[(1 + i) * 8 + j], zd[j]);
        }
        int idx = 9;
#pragma unroll
        for (int i = 0; i < 8; i++)
#pragma unroll
            for (int k = i; k < 8; k++) {
                const float q = z[i] * z[k];
#pragma unroll
                for (int j = 0; j < 8; j++)
                    zd[j] = fmaf(q, Xis[idx * 8 + j], zd[j]);
                idx++;
            }
#pragma unroll
        for (int j = 0; j < 8; j++) z[j] = fmaf(zd[j], dt, z[j]);
    }

    float h[8];
#pragma unroll
    for (int e = 0; e < 8; e++) h[e] = __half2float(__float2half_rn(z[e]));
    uint4 qh, ql, qz;
    qh.x = pack_h2(h[0], h[1]); qh.y = pack_h2(h[2], h[3]);
    qh.z = pack_h2(h[4], h[5]); qh.w = pack_h2(h[6], h[7]);
    ql.x = pack_h2(z[0] - h[0], z[1] - h[1]); ql.y = pack_h2(z[2] - h[2], z[3] - h[3]);
    ql.z = pack_h2(z[4] - h[4], z[5] - h[5]); ql.w = pack_h2(z[6] - h[6], z[7] - h[7]);
    qz.x = qz.y = qz.z = qz.w = 0u;
    uint4* ph = (uint4*)(Zhi + row * 32);
    uint4* pl = (uint4*)(Zlo + row * 32);
    ph[0] = qh; ph[1] = qz; ph[2] = qz; ph[3] = qz;
    pl[0] = ql; pl[1] = qz; pl[2] = qz; pl[3] = qz;
}

// ============================================================================
extern "C" void kernel_launch(void* const* d_in, const int* in_sizes, int n_in,
                              void* d_out, int out_size)
{
    (void)in_sizes; (void)n_in; (void)out_size;
    const float* x0   = (const float*)d_in[0];
    const float* dtn  = (const float*)d_in[1];
    const float* eW1  = (const float*)d_in[4];
    const float* eb1  = (const float*)d_in[5];
    const float* eg1  = (const float*)d_in[6];
    const float* ebe1 = (const float*)d_in[7];
    const float* eW2  = (const float*)d_in[8];
    const float* eb2  = (const float*)d_in[9];
    const float* eg2  = (const float*)d_in[10];
    const float* ebe2 = (const float*)d_in[11];
    const float* eW3  = (const float*)d_in[12];
    const float* eb3  = (const float*)d_in[13];
    const float* dW1  = (const float*)d_in[14];
    const float* db1  = (const float*)d_in[15];
    const float* dg1  = (const float*)d_in[16];
    const float* dbe1 = (const float*)d_in[17];
    const float* dW2  = (const float*)d_in[18];
    const float* db2  = (const float*)d_in[19];
    const float* dg2  = (const float*)d_in[20];
    const float* dbe2 = (const float*)d_in[21];
    const float* dW3  = (const float*)d_in[22];
    const float* db3  = (const float*)d_in[23];
    const float* Xi   = (const float*)d_in[24];
    float* out = (float*)d_out;

    __half *hAh, *hAl, *hBh, *hBl, *xh, *xl, *zh, *zl;
    __half *w1, *w2, *d1, *d2, *d3;
    float* z0;
    cudaGetSymbolAddress((void**)&hAh, g_hA_hi); cudaGetSymbolAddress((void**)&hAl, g_hA_lo);
    cudaGetSymbolAddress((void**)&hBh, g_hB_hi); cudaGetSymbolAddress((void**)&hBl, g_hB_lo);
    cudaGetSymbolAddress((void**)&xh,  g_x_hi);  cudaGetSymbolAddress((void**)&xl,  g_x_lo);
    cudaGetSymbolAddress((void**)&zh,  g_z_hi);  cudaGetSymbolAddress((void**)&zl,  g_z_lo);
    cudaGetSymbolAddress((void**)&z0,  g_z0);
    cudaGetSymbolAddress((void**)&w1, g_w1);
    cudaGetSymbolAddress((void**)&w2, g_w2);
    cudaGetSymbolAddress((void**)&d1, g_d1);
    cudaGetSymbolAddress((void**)&d2, g_d2);
    cudaGetSymbolAddress((void**)&d3, g_d3);

    cudaFuncSetAttribute(wide_mma_kernel<64, false>,
        cudaFuncAttributeMaxDynamicSharedMemorySize, SM_WIDE);
    cudaFuncSetAttribute(wide_mma_kernel<32, false>,
        cudaFuncAttributeMaxDynamicSharedMemorySize, SM_WIDE);
    cudaFuncSetAttribute(wide_mma_kernel<512, false>,
        cudaFuncAttributeMaxDynamicSharedMemorySize, SM_WIDE);
    cudaFuncSetAttribute(wide_mma_kernel<512, true>,
        cudaFuncAttributeMaxDynamicSharedMemorySize, SM_WIDE);
    cudaFuncSetAttribute(out_mma_kernel,
        cudaFuncAttributeMaxDynamicSharedMemorySize, SM_OUT);

    // ---- prep: single launch for all weights, one for x ----
    prep_all_kernel<<<(SEG4 + 255) / 256, 256>>>(eW1, eW2, dW1, dW2, dW3,
                                                 w1, w2, d1, d2, d3);
    prep_x_kernel<<<(BATCH * 64) / 256, 256>>>(x0, xh, xl);

    const int nwide = BATCH / 32;    // 4096

    // ---- pipeline ----
    wide_mma_kernel<64, false><<<nwide, 256, SM_WIDE>>>(
        xh, xl, w1, eb1, eg1, ebe1, hAh, hAl, nullptr, nullptr, nullptr);
    wide_mma_kernel<512, true><<<nwide, 256, SM_WIDE>>>(
        hAh, hAl, w2, eb2, eg2, ebe2, nullptr, nullptr, eW3, eb3, z0);
    integrate_kernel<<<BATCH / 256, 256>>>(z0, dtn, Xi, zh, zl);
    wide_mma_kernel<32, false><<<nwide, 256, SM_WIDE>>>(
        zh, zl, d1, db1, dg1, dbe1, hAh, hAl, nullptr, nullptr, nullptr);
    wide_mma_kernel<512, false><<<nwide, 256, SM_WIDE>>>(
        hAh, hAl, d2, db2, dg2, dbe2, hBh, hBl, nullptr, nullptr, nullptr);
    out_mma_kernel<<<BATCH / 128, 256, SM_OUT>>>(hBh, hBl, d3, db3, out);
}

// round 11
// speedup vs baseline: 1.2265x; 1.2265x over previous
#include <cuda_runtime.h>
#include <cuda_fp16.h>
#include <math.h>
#include <stdint.h>

#define BATCH   131072
#define HID     512
#define LDIM    8
#define NTH     45
#define NSTEPS  20

// ============================================================================
// Baseline-PTX tensor helpers (compute_103-safe: ldmatrix + mma.sync only)
// ============================================================================
__device__ __forceinline__ uint32_t smem_u32(const void* p) {
    uint32_t a;
    asm("{ .reg .u64 t; cvta.to.shared.u64 t, %1; cvt.u32.u64 %0, t; }"
        : "=r"(a) : "l"(p));
    return a;
}

#define LDSM4(r0, r1, r2, r3, addr) \
    asm volatile("ldmatrix.sync.aligned.m8n8.x4.shared.b16 {%0,%1,%2,%3}, [%4];" \
        : "=r"(r0), "=r"(r1), "=r"(r2), "=r"(r3) : "r"(addr))

// fp16 inputs, fp32 accumulate
#define MMA16816(d, a, b0, b1) \
    asm volatile("mma.sync.aligned.m16n8k16.row.col.f32.f16.f16.f32 " \
        "{%0,%1,%2,%3},{%4,%5,%6,%7},{%8,%9},{%0,%1,%2,%3};" \
        : "+f"((d)[0]), "+f"((d)[1]), "+f"((d)[2]), "+f"((d)[3]) \
        : "r"((a)[0]), "r"((a)[1]), "r"((a)[2]), "r"((a)[3]), \
          "r"(b0), "r"(b1))

__device__ __forceinline__ void cp16(uint32_t dst, const void* src) {
    asm volatile("cp.async.cg.shared.global [%0], [%1], 16;"
        :: "r"(dst), "l"(src));
}
#define CP_COMMIT() asm volatile("cp.async.commit_group;" ::: "memory")
#define CP_WAIT(n)  asm volatile("cp.async.wait_group %0;" :: "n"(n) : "memory")

__device__ __forceinline__ uint32_t pack_h2(float a, float b) {
    __half2 t = __floats2half2_rn(a, b);
    return reinterpret_cast<uint32_t&>(t);
}

// ============================================================================
// Scratch: activations single fp16 row-major. Weights single fp16,
// pre-transposed WT[n][kpad], zero-pad k>=K.
// ============================================================================
__device__ __half g_hA[BATCH * HID];
__device__ __half g_hB[BATCH * HID];
__device__ __half g_x[BATCH * 64];
__device__ __half g_z[BATCH * 32];    // zt padded to 32 cols
__device__ float  g_z0[BATCH * LDIM];

__device__ __half g_w1[512 * 64];     // enc_W1  KPAD=64
__device__ __half g_w2[512 * 512];    // enc_W2  KPAD=512
__device__ __half g_d1[512 * 32];     // dec_W1  K=8 -> KPAD=32
__device__ __half g_d2[512 * 512];    // dec_W2  KPAD=512
__device__ __half g_d3[64 * 512];     // dec_W3  KPAD=512

// ============================================================================
// prep: all five weights in ONE launch (transpose + fp16 round + zero-pad)
// ============================================================================
#define SEG0 32768            // w1  (K=64,  N=512, KPAD=64)
#define SEG1 (SEG0 + 262144)  // w2  (K=512, N=512, KPAD=512)
#define SEG2 (SEG1 + 16384)   // d1  (K=8,   N=512, KPAD=32)
#define SEG3 (SEG2 + 262144)  // d2  (K=512, N=512, KPAD=512)
#define SEG4 (SEG3 + 32768)   // d3  (K=512, N=64,  KPAD=512)

__global__ void prep_all_kernel(const float* __restrict__ eW1,
                                const float* __restrict__ eW2,
                                const float* __restrict__ dW1,
                                const float* __restrict__ dW2,
                                const float* __restrict__ dW3,
                                __half* __restrict__ w1, __half* __restrict__ w2,
                                __half* __restrict__ d1, __half* __restrict__ d2,
                                __half* __restrict__ d3)
{
    int idx = blockIdx.x * 256 + threadIdx.x;
    if (idx >= SEG4) return;
    const float* W; __half* O; int K, N, KPAD, off;
    if (idx < SEG0)      { W = eW1; O = w1; K = 64;  N = 512; KPAD = 64;  off = 0;    }
    else if (idx < SEG1) { W = eW2; O = w2; K = 512; N = 512; KPAD = 512; off = SEG0; }
    else if (idx < SEG2) { W = dW1; O = d1; K = 8;   N = 512; KPAD = 32;  off = SEG1; }
    else if (idx < SEG3) { W = dW2; O = d2; K = 512; N = 512; KPAD = 512; off = SEG2; }
    else                 { W = dW3; O = d3; K = 512; N = 64;  KPAD = 512; off = SEG3; }
    int i = idx - off;
    int n = i / KPAD, k = i % KPAD;
    float v = (k < K) ? W[(size_t)k * N + n] : 0.f;
    O[i] = __float2half_rn(v);
}

__global__ void prep_x_kernel(const float* __restrict__ x0,
                              __half* __restrict__ xo)
{
    size_t idx = (size_t)blockIdx.x * 256 + threadIdx.x;
    xo[idx] = __float2half_rn(x0[idx]);
}

// ============================================================================
// wide layer: O[B,512] = SiLU(LN(A[B,KPAD] @ W + b)), single fp16 operands,
// fp32 accumulate. CTA: M=64, N=512 (full row -> fused LN). 512 thr = 16
// warps (2Mx8N), warp tile m32 x n64. BK=32, 2-stage cp.async double buffer.
// smem rows padded to 80B -> conflict-free ldmatrix.
// WRITE_Z: skip activation store; fuse z0 = tanh(h @ W3 + b3).
// ============================================================================
#define LDR 80
#define WST      46080                          // bytes per stage
#define WS_A(s)  ((s) * WST)                    // A: 64*80 = 5120
#define WS_B(s)  ((s) * WST + 5120)             // B: 512*80 = 40960
#define WS_PAR   92160                          // bias/g/beta 3x2048
#define WS_RED   98304                          // sums/mu/rs 4x256
#define WS_Z     99328                          // 64x8 fp32 = 2048
#define WS_W3    101376                         // 512x8 fp32 = 16384
#define SM_WIDE  117760

template<int KPAD, bool WRITE_Z>
__global__ __launch_bounds__(512, 1)
void wide_mma_kernel(const __half* __restrict__ A,
                     const __half* __restrict__ W,
                     const float* __restrict__ bias,
                     const float* __restrict__ gamma,
                     const float* __restrict__ beta,
                     __half* __restrict__ O,
                     const float* __restrict__ W3,
                     const float* __restrict__ b3,
                     float* __restrict__ z0out)
{
    constexpr int NC = KPAD / 32;
    extern __shared__ char smem[];
    const uint32_t sb = smem_u32(smem);
    const int tid = threadIdx.x, lane = tid & 31, w = tid >> 5;
    const int warpM = w >> 3, warpN = w & 7;          // 2 x 8
    const int nbase = warpN * 64;
    const int tile = blockIdx.x;                      // 64-row tile

    float* sBias = (float*)(smem + WS_PAR);
    float* sG    = (float*)(smem + WS_PAR + 2048);
    float* sBe   = (float*)(smem + WS_PAR + 4096);
    float* sSum  = (float*)(smem + WS_RED);
    float* sSum2 = (float*)(smem + WS_RED + 256);
    float* sMu   = (float*)(smem + WS_RED + 512);
    float* sRs   = (float*)(smem + WS_RED + 768);
    float* sZ    = (float*)(smem + WS_Z);
    float* sW3   = (float*)(smem + WS_W3);

    sBias[tid] = bias[tid]; sG[tid] = gamma[tid]; sBe[tid] = beta[tid];
    if (tid < 64) { sSum[tid] = 0.f; sSum2[tid] = 0.f; }
    if (WRITE_Z) {
        sZ[tid] = 0.f;
        for (int i = tid; i < 512 * 8; i += 512) sW3[i] = W3[i];
    }

    // chunk loader: B (512 rows x 64B), A (64 rows x 64B)
    auto load_chunk = [&](int c, int sel) {
        const int kbase = c * 32;
        const uint32_t bB = sb + WS_B(sel);
        for (int i = tid; i < 2048; i += 512) {
            const int row = i >> 2, j = i & 3;
            cp16(bB + row * LDR + j * 16,
                 (const char*)W + ((size_t)row * KPAD + kbase) * 2 + j * 16);
        }
        if (tid < 256) {
            const int row = tid >> 2, j = tid & 3;
            cp16(sb + WS_A(sel) + row * LDR + j * 16,
                 (const char*)A + (((size_t)tile * 64 + row) * KPAD + kbase) * 2 + j * 16);
        }
        CP_COMMIT();
    };

    load_chunk(0, 0);
    if (NC > 1) load_chunk(1, 1); else CP_COMMIT();

    float acc[2][8][4];
#pragma unroll
    for (int i = 0; i < 2; i++)
#pragma unroll
        for (int j = 0; j < 8; j++)
#pragma unroll
            for (int r = 0; r < 4; r++) acc[i][j][r] = 0.f;

    const int arow = ((lane >> 3) & 1) * 8 + (lane & 7);
    const int acol = (lane >> 4) * 8;
    const int brow = ((lane >> 4) & 1) * 8 + (lane & 7);
    const int bcol = ((lane >> 3) & 1) * 8;

#pragma unroll 1
    for (int c = 0; c < NC; c++) {
        if (c + 1 < NC) CP_WAIT(1); else CP_WAIT(0);
        __syncthreads();
        const int sel = c & 1;
        const uint32_t bA = sb + WS_A(sel);
        const uint32_t bB = sb + WS_B(sel);
#pragma unroll
        for (int ks = 0; ks < 32; ks += 16) {
            uint32_t ah[2][4];
#pragma unroll
            for (int mf = 0; mf < 2; mf++) {
                const uint32_t ao = (uint32_t)((warpM * 32 + mf * 16 + arow) * LDR
                                               + (ks + acol) * 2);
                LDSM4(ah[mf][0], ah[mf][1], ah[mf][2], ah[mf][3], bA + ao);
            }
#pragma unroll
            for (int nq = 0; nq < 4; nq++) {
                const uint32_t bo = (uint32_t)((nbase + nq * 16 + brow) * LDR
                                               + (ks + bcol) * 2);
                uint32_t b[4];
                LDSM4(b[0], b[1], b[2], b[3], bB + bo);
#pragma unroll
                for (int mf = 0; mf < 2; mf++) {
                    MMA16816(acc[mf][nq * 2],     ah[mf], b[0], b[1]);
                    MMA16816(acc[mf][nq * 2 + 1], ah[mf], b[2], b[3]);
                }
            }
        }
        __syncthreads();
        if (c + 2 < NC) load_chunk(c + 2, sel);
    }

    // ---------------- epilogue: bias -> LN stats ----------------------------
#pragma unroll
    for (int mf = 0; mf < 2; mf++)
#pragma unroll
        for (int rh = 0; rh < 2; rh++) {
            float s = 0.f, s2 = 0.f;
#pragma unroll
            for (int idx = 0; idx < 8; idx++) {
                const int c0 = nbase + idx * 8 + (lane & 3) * 2;
                float v0 = acc[mf][idx][rh * 2]     + sBias[c0];
                float v1 = acc[mf][idx][rh * 2 + 1] + sBias[c0 + 1];
                acc[mf][idx][rh * 2] = v0; acc[mf][idx][rh * 2 + 1] = v1;
                s += v0 + v1; s2 += v0 * v0 + v1 * v1;
            }
            s  += __shfl_xor_sync(0xffffffffu, s, 1);
            s  += __shfl_xor_sync(0xffffffffu, s, 2);
            s2 += __shfl_xor_sync(0xffffffffu, s2, 1);
            s2 += __shfl_xor_sync(0xffffffffu, s2, 2);
            if ((lane & 3) == 0) {
                const int row = warpM * 32 + mf * 16 + (lane >> 2) + rh * 8;
                atomicAdd(&sSum[row], s);
                atomicAdd(&sSum2[row], s2);
            }
        }
    __syncthreads();
    if (tid < 64) {
        const float mu = sSum[tid] * (1.f / 512.f);
        const float var = sSum2[tid] * (1.f / 512.f) - mu * mu;
        sMu[tid] = mu; sRs[tid] = rsqrtf(var + 1e-5f);
    }
    __syncthreads();

    // ---------------- LN + SiLU, store fp16 or fused z = tanh(h@W3+b3) ------
#pragma unroll
    for (int mf = 0; mf < 2; mf++)
#pragma unroll
        for (int rh = 0; rh < 2; rh++) {
            const int row = warpM * 32 + mf * 16 + (lane >> 2) + rh * 8;
            const float mu = sMu[row], rs = sRs[row];
            float zp[8];
            if (WRITE_Z) {
#pragma unroll
                for (int j = 0; j < 8; j++) zp[j] = 0.f;
            }
            const size_t rowg = (size_t)tile * 64 + row;
#pragma unroll
            for (int idx = 0; idx < 8; idx++) {
                const int c0 = nbase + idx * 8 + (lane & 3) * 2;
                float y0 = (acc[mf][idx][rh * 2]     - mu) * rs * sG[c0]     + sBe[c0];
                float y1 = (acc[mf][idx][rh * 2 + 1] - mu) * rs * sG[c0 + 1] + sBe[c0 + 1];
                y0 = y0 * (1.f / (1.f + __expf(-y0)));
                y1 = y1 * (1.f / (1.f + __expf(-y1)));
                if (WRITE_Z) {
                    const float* w0 = sW3 + c0 * 8;
#pragma unroll
                    for (int j = 0; j < 8; j++) {
                        zp[j] = fmaf(y0, w0[j], zp[j]);
                        zp[j] = fmaf(y1, w0[8 + j], zp[j]);
                    }
                } else {
                    *(uint32_t*)(O + rowg * 512 + c0) = pack_h2(y0, y1);
                }
            }
            if (WRITE_Z) {
#pragma unroll
                for (int j = 0; j < 8; j++) {
                    zp[j] += __shfl_xor_sync(0xffffffffu, zp[j], 1);
                    zp[j] += __shfl_xor_sync(0xffffffffu, zp[j], 2);
                }
                if ((lane & 3) == 0)
#pragma unroll
                    for (int j = 0; j < 8; j++)
                        atomicAdd(&sZ[row * 8 + j], zp[j]);
            }
        }

    if (WRITE_Z) {
        __syncthreads();
        if (tid < 64) {
            const size_t rowg = (size_t)tile * 64 + tid;
#pragma unroll
            for (int j = 0; j < 8; j++)
                z0out[rowg * 8 + j] = tanhf(sZ[tid * 8 + j] + __ldg(b3 + j));
        }
    }
}

// ============================================================================
// out layer: out[B,64] = A[B,512] @ W3 + b3 (fp32 out, no LN).
// CTA: M=128, N=64. 256 thr = 8 warps (4Mx2N), warp m32 x n32. BK=32, 2-stage.
// ============================================================================
#define OST      15360
#define OS_A(s)  ((s) * OST)                    // 128*80 = 10240
#define OS_B(s)  ((s) * OST + 10240)            // 64*80  = 5120
#define SM_OUT   30720

__global__ __launch_bounds__(256, 2)
void out_mma_kernel(const __half* __restrict__ A,
                    const __half* __restrict__ W,
                    const float* __restrict__ bias,
                    float* __restrict__ out)
{
    constexpr int NC = 16;
    extern __shared__ char smem[];
    const uint32_t sb = smem_u32(smem);
    const int tid = threadIdx.x, lane = tid & 31, w = tid >> 5;
    const int warpM = w >> 1, warpN = w & 1;
    const int nbase = warpN * 32;
    const int tile = blockIdx.x;

    auto load_chunk = [&](int c, int sel) {
        const int kbase = c * 32;
        {
            const int row = tid >> 2, j = tid & 3;   // 64 rows x 4
            cp16(sb + OS_B(sel) + row * LDR + j * 16,
                 (const char*)W + ((size_t)row * 512 + kbase) * 2 + j * 16);
        }
        for (int i = tid; i < 512; i += 256) {       // 128 rows x 4
            const int row = i >> 2, j = i & 3;
            cp16(sb + OS_A(sel) + row * LDR + j * 16,
                 (const char*)A + (((size_t)tile * 128 + row) * 512 + kbase) * 2 + j * 16);
        }
        CP_COMMIT();
    };

    load_chunk(0, 0);
    load_chunk(1, 1);

    float acc[2][4][4];
#pragma unroll
    for (int i = 0; i < 2; i++)
#pragma unroll
        for (int j = 0; j < 4; j++)
#pragma unroll
            for (int r = 0; r < 4; r++) acc[i][j][r] = 0.f;

    const int arow = ((lane >> 3) & 1) * 8 + (lane & 7);
    const int acol = (lane >> 4) * 8;
    const int brow = ((lane >> 4) & 1) * 8 + (lane & 7);
    const int bcol = ((lane >> 3) & 1) * 8;

#pragma unroll 1
    for (int c = 0; c < NC; c++) {
        if (c + 1 < NC) CP_WAIT(1); else CP_WAIT(0);
        __syncthreads();
        const int sel = c & 1;
        const uint32_t bA = sb + OS_A(sel);
        const uint32_t bB = sb + OS_B(sel);
#pragma unroll
        for (int ks = 0; ks < 32; ks += 16) {
            uint32_t ah[2][4];
#pragma unroll
            for (int mf = 0; mf < 2; mf++) {
                const uint32_t ao = (uint32_t)((warpM * 32 + mf * 16 + arow) * LDR
                                               + (ks + acol) * 2);
                LDSM4(ah[mf][0], ah[mf][1], ah[mf][2], ah[mf][3], bA + ao);
            }
#pragma unroll
            for (int nq = 0; nq < 2; nq++) {
                const uint32_t bo = (uint32_t)((nbase + nq * 16 + brow) * LDR
                                               + (ks + bcol) * 2);
                uint32_t b[4];
                LDSM4(b[0], b[1], b[2], b[3], bB + bo);
#pragma unroll
                for (int mf = 0; mf < 2; mf++) {
                    MMA16816(acc[mf][nq * 2],     ah[mf], b[0], b[1]);
                    MMA16816(acc[mf][nq * 2 + 1], ah[mf], b[2], b[3]);
                }
            }
        }
        __syncthreads();
        if (c + 2 < NC) load_chunk(c + 2, sel);
    }

#pragma unroll
    for (int mf = 0; mf < 2; mf++)
#pragma unroll
        for (int rh = 0; rh < 2; rh++) {
            const int row = warpM * 32 + mf * 16 + (lane >> 2) + rh * 8;
            const size_t rowg = (size_t)tile * 128 + row;
#pragma unroll
            for (int idx = 0; idx < 4; idx++) {
                const int c0 = nbase + idx * 8 + (lane & 3) * 2;
                float2 o;
                o.x = acc[mf][idx][rh * 2]     + __ldg(bias + c0);
                o.y = acc[mf][idx][rh * 2 + 1] + __ldg(bias + c0 + 1);
                *(float2*)(out + rowg * 64 + c0) = o;
            }
        }
}

// ============================================================================
// integrator: 20 Euler steps; outputs fp16 row-major padded to 32 cols
// ============================================================================
__global__ __launch_bounds__(256, 4)
void integrate_kernel(const float* __restrict__ z0,
                      const float* __restrict__ dtv,
                      const float* __restrict__ Xi,
                      __half* __restrict__ Z)
{
    __shared__ float Xis[NTH * LDIM];
    for (int i = threadIdx.x; i < NTH * LDIM; i += 256) Xis[i] = Xi[i];
    __syncthreads();

    const size_t row = (size_t)blockIdx.x * 256 + threadIdx.x;
    float z[8];
    *(float4*)&z[0] = *(const float4*)(z0 + row * 8);
    *(float4*)&z[4] = *(const float4*)(z0 + row * 8 + 4);
    const float dt = dtv[row] * (1.f / (float)NSTEPS);

#pragma unroll 1
    for (int s = 0; s < NSTEPS; s++) {
        float zd[8];
#pragma unroll
        for (int j = 0; j < 8; j++) zd[j] = Xis[j];
#pragma unroll
        for (int i = 0; i < 8; i++) {
            const float t = z[i];
#pragma unroll
            for (int j = 0; j < 8; j++)
                zd[j] = fmaf(t, Xis[(1 + i) * 8 + j], zd[j]);
        }
        int idx = 9;
#pragma unroll
        for (int i = 0; i < 8; i++)
#pragma unroll
            for (int k = i; k < 8; k++) {
                const float q = z[i] * z[k];
#pragma unroll
                for (int j = 0; j < 8; j++)
                    zd[j] = fmaf(q, Xis[idx * 8 + j], zd[j]);
                idx++;
            }
#pragma unroll
        for (int j = 0; j < 8; j++) z[j] = fmaf(zd[j], dt, z[j]);
    }

    uint4 qh, qz;
    qh.x = pack_h2(z[0], z[1]); qh.y = pack_h2(z[2], z[3]);
    qh.z = pack_h2(z[4], z[5]); qh.w = pack_h2(z[6], z[7]);
    qz.x = qz.y = qz.z = qz.w = 0u;
    uint4* ph = (uint4*)(Z + row * 32);
    ph[0] = qh; ph[1] = qz;
}

// ============================================================================
extern "C" void kernel_launch(void* const* d_in, const int* in_sizes, int n_in,
                              void* d_out, int out_size)
{
    (void)in_sizes; (void)n_in; (void)out_size;
    const float* x0   = (const float*)d_in[0];
    const float* dtn  = (const float*)d_in[1];
    const float* eW1  = (const float*)d_in[4];
    const float* eb1  = (const float*)d_in[5];
    const float* eg1  = (const float*)d_in[6];
    const float* ebe1 = (const float*)d_in[7];
    const float* eW2  = (const float*)d_in[8];
    const float* eb2  = (const float*)d_in[9];
    const float* eg2  = (const float*)d_in[10];
    const float* ebe2 = (const float*)d_in[11];
    const float* eW3  = (const float*)d_in[12];
    const float* eb3  = (const float*)d_in[13];
    const float* dW1  = (const float*)d_in[14];
    const float* db1  = (const float*)d_in[15];
    const float* dg1  = (const float*)d_in[16];
    const float* dbe1 = (const float*)d_in[17];
    const float* dW2  = (const float*)d_in[18];
    const float* db2  = (const float*)d_in[19];
    const float* dg2  = (const float*)d_in[20];
    const float* dbe2 = (const float*)d_in[21];
    const float* dW3  = (const float*)d_in[22];
    const float* db3  = (const float*)d_in[23];
    const float* Xi   = (const float*)d_in[24];
    float* out = (float*)d_out;

    __half *hA, *hB, *xh, *zh;
    __half *w1, *w2, *d1, *d2, *d3;
    float* z0;
    cudaGetSymbolAddress((void**)&hA, g_hA);
    cudaGetSymbolAddress((void**)&hB, g_hB);
    cudaGetSymbolAddress((void**)&xh, g_x);
    cudaGetSymbolAddress((void**)&zh, g_z);
    cudaGetSymbolAddress((void**)&z0, g_z0);
    cudaGetSymbolAddress((void**)&w1, g_w1);
    cudaGetSymbolAddress((void**)&w2, g_w2);
    cudaGetSymbolAddress((void**)&d1, g_d1);
    cudaGetSymbolAddress((void**)&d2, g_d2);
    cudaGetSymbolAddress((void**)&d3, g_d3);

    cudaFuncSetAttribute(wide_mma_kernel<64, false>,
        cudaFuncAttributeMaxDynamicSharedMemorySize, SM_WIDE);
    cudaFuncSetAttribute(wide_mma_kernel<32, false>,
        cudaFuncAttributeMaxDynamicSharedMemorySize, SM_WIDE);
    cudaFuncSetAttribute(wide_mma_kernel<512, false>,
        cudaFuncAttributeMaxDynamicSharedMemorySize, SM_WIDE);
    cudaFuncSetAttribute(wide_mma_kernel<512, true>,
        cudaFuncAttributeMaxDynamicSharedMemorySize, SM_WIDE);
    cudaFuncSetAttribute(out_mma_kernel,
        cudaFuncAttributeMaxDynamicSharedMemorySize, SM_OUT);

    // ---- prep: single launch for all weights, one for x ----
    prep_all_kernel<<<(SEG4 + 255) / 256, 256>>>(eW1, eW2, dW1, dW2, dW3,
                                                 w1, w2, d1, d2, d3);
    prep_x_kernel<<<(BATCH * 64) / 256, 256>>>(x0, xh);

    const int nwide = BATCH / 64;    // 2048

    // ---- pipeline ----
    wide_mma_kernel<64, false><<<nwide, 512, SM_WIDE>>>(
        xh, w1, eb1, eg1, ebe1, hA, nullptr, nullptr, nullptr);
    wide_mma_kernel<512, true><<<nwide, 512, SM_WIDE>>>(
        hA, w2, eb2, eg2, ebe2, nullptr, eW3, eb3, z0);
    integrate_kernel<<<BATCH / 256, 256>>>(z0, dtn, Xi, zh);
    wide_mma_kernel<32, false><<<nwide, 512, SM_WIDE>>>(
        zh, d1, db1, dg1, dbe1, hA, nullptr, nullptr, nullptr);
    wide_mma_kernel<512, false><<<nwide, 512, SM_WIDE>>>(
        hA, d2, db2, dg2, dbe2, hB, nullptr, nullptr, nullptr);
    out_mma_kernel<<<BATCH / 128, 256, SM_OUT>>>(hB, d3, db3, out);
}

// round 12
// speedup vs baseline: 1.2506x; 1.0197x over previous
#include <cuda_runtime.h>
#include <cuda_fp16.h>
#include <math.h>
#include <stdint.h>

#define BATCH   131072
#define HID     512
#define LDIM    8
#define NTH     45
#define NSTEPS  20

// ============================================================================
// Baseline-PTX tensor helpers (compute_103-safe: ldmatrix + mma.sync only)
// ============================================================================
__device__ __forceinline__ uint32_t smem_u32(const void* p) {
    uint32_t a;
    asm("{ .reg .u64 t; cvta.to.shared.u64 t, %1; cvt.u32.u64 %0, t; }"
        : "=r"(a) : "l"(p));
    return a;
}

#define LDSM4(r0, r1, r2, r3, addr) \
    asm volatile("ldmatrix.sync.aligned.m8n8.x4.shared.b16 {%0,%1,%2,%3}, [%4];" \
        : "=r"(r0), "=r"(r1), "=r"(r2), "=r"(r3) : "r"(addr))

// fp16 inputs, fp32 accumulate
#define MMA16816(d, a, b0, b1) \
    asm volatile("mma.sync.aligned.m16n8k16.row.col.f32.f16.f16.f32 " \
        "{%0,%1,%2,%3},{%4,%5,%6,%7},{%8,%9},{%0,%1,%2,%3};" \
        : "+f"((d)[0]), "+f"((d)[1]), "+f"((d)[2]), "+f"((d)[3]) \
        : "r"((a)[0]), "r"((a)[1]), "r"((a)[2]), "r"((a)[3]), \
          "r"(b0), "r"(b1))

__device__ __forceinline__ void cp16(uint32_t dst, const void* src) {
    asm volatile("cp.async.cg.shared.global [%0], [%1], 16;"
        :: "r"(dst), "l"(src));
}
#define CP_COMMIT() asm volatile("cp.async.commit_group;" ::: "memory")
#define CP_WAIT(n)  asm volatile("cp.async.wait_group %0;" :: "n"(n) : "memory")

__device__ __forceinline__ uint32_t pack_h2(float a, float b) {
    __half2 t = __floats2half2_rn(a, b);
    return reinterpret_cast<uint32_t&>(t);
}

// ============================================================================
// Scratch: activations single fp16 row-major. Weights single fp16,
// pre-transposed WT[n][kpad], zero-pad k>=K.
// ============================================================================
__device__ __half g_hA[BATCH * HID];
__device__ __half g_hB[BATCH * HID];
__device__ __half g_x[BATCH * 64];
__device__ __half g_z[BATCH * 64];    // zt padded to 64 cols
__device__ float  g_z0[BATCH * LDIM];

__device__ __half g_w1[512 * 64];     // enc_W1  KPAD=64
__device__ __half g_w2[512 * 512];    // enc_W2  KPAD=512
__device__ __half g_d1[512 * 64];     // dec_W1  K=8 -> KPAD=64
__device__ __half g_d2[512 * 512];    // dec_W2  KPAD=512
__device__ __half g_d3[64 * 512];     // dec_W3  KPAD=512

// ============================================================================
// prep: all five weights in ONE launch (transpose + fp16 round + zero-pad)
// ============================================================================
#define SEG0 32768            // w1  (K=64,  N=512, KPAD=64)
#define SEG1 (SEG0 + 262144)  // w2  (K=512, N=512, KPAD=512)
#define SEG2 (SEG1 + 32768)   // d1  (K=8,   N=512, KPAD=64)
#define SEG3 (SEG2 + 262144)  // d2  (K=512, N=512, KPAD=512)
#define SEG4 (SEG3 + 32768)   // d3  (K=512, N=64,  KPAD=512)

__global__ void prep_all_kernel(const float* __restrict__ eW1,
                                const float* __restrict__ eW2,
                                const float* __restrict__ dW1,
                                const float* __restrict__ dW2,
                                const float* __restrict__ dW3,
                                __half* __restrict__ w1, __half* __restrict__ w2,
                                __half* __restrict__ d1, __half* __restrict__ d2,
                                __half* __restrict__ d3)
{
    int idx = blockIdx.x * 256 + threadIdx.x;
    if (idx >= SEG4) return;
    const float* W; __half* O; int K, N, KPAD, off;
    if (idx < SEG0)      { W = eW1; O = w1; K = 64;  N = 512; KPAD = 64;  off = 0;    }
    else if (idx < SEG1) { W = eW2; O = w2; K = 512; N = 512; KPAD = 512; off = SEG0; }
    else if (idx < SEG2) { W = dW1; O = d1; K = 8;   N = 512; KPAD = 64;  off = SEG1; }
    else if (idx < SEG3) { W = dW2; O = d2; K = 512; N = 512; KPAD = 512; off = SEG2; }
    else                 { W = dW3; O = d3; K = 512; N = 64;  KPAD = 512; off = SEG3; }
    int i = idx - off;
    int n = i / KPAD, k = i % KPAD;
    float v = (k < K) ? W[(size_t)k * N + n] : 0.f;
    O[i] = __float2half_rn(v);
}

__global__ void prep_x_kernel(const float* __restrict__ x0,
                              __half* __restrict__ xo)
{
    size_t idx = (size_t)blockIdx.x * 256 + threadIdx.x;
    xo[idx] = __float2half_rn(x0[idx]);
}

// ============================================================================
// wide layer: O[B,512] = SiLU(LN(A[B,KPAD] @ W + b)), single fp16 operands,
// fp32 accumulate. CTA: M=64, N=512 (full row -> fused LN). 512 thr = 16
// warps (2Mx8N), warp tile m32 x n64. BK=64, 2-stage cp.async double buffer
// (half the barrier/CP_WAIT convoys vs BK=32).
// smem rows 144B (128B data + 16B pad) -> conflict-free ldmatrix.
// WRITE_Z: skip activation store; fuse z0 = tanh(h @ W3 + b3).
// ============================================================================
#define LDR 144
#define WST      82944                          // bytes per stage
#define WS_A(s)  ((s) * WST)                    // A: 64*144  = 9216
#define WS_B(s)  ((s) * WST + 9216)             // B: 512*144 = 73728
#define WS_PAR   165888                         // bias/g/beta 3x2048
#define WS_RED   172032                         // sums/mu/rs 4x256
#define WS_Z     173056                         // 64x8 fp32 = 2048
#define WS_W3    175104                         // 512x8 fp32 = 16384
#define SM_WIDE  191488

template<int KPAD, bool WRITE_Z>
__global__ __launch_bounds__(512, 1)
void wide_mma_kernel(const __half* __restrict__ A,
                     const __half* __restrict__ W,
                     const float* __restrict__ bias,
                     const float* __restrict__ gamma,
                     const float* __restrict__ beta,
                     __half* __restrict__ O,
                     const float* __restrict__ W3,
                     const float* __restrict__ b3,
                     float* __restrict__ z0out)
{
    constexpr int NC = KPAD / 64;
    extern __shared__ char smem[];
    const uint32_t sb = smem_u32(smem);
    const int tid = threadIdx.x, lane = tid & 31, w = tid >> 5;
    const int warpM = w >> 3, warpN = w & 7;          // 2 x 8
    const int nbase = warpN * 64;
    const int tile = blockIdx.x;                      // 64-row tile

    float* sBias = (float*)(smem + WS_PAR);
    float* sG    = (float*)(smem + WS_PAR + 2048);
    float* sBe   = (float*)(smem + WS_PAR + 4096);
    float* sSum  = (float*)(smem + WS_RED);
    float* sSum2 = (float*)(smem + WS_RED + 256);
    float* sMu   = (float*)(smem + WS_RED + 512);
    float* sRs   = (float*)(smem + WS_RED + 768);
    float* sZ    = (float*)(smem + WS_Z);
    float* sW3   = (float*)(smem + WS_W3);

    sBias[tid] = bias[tid]; sG[tid] = gamma[tid]; sBe[tid] = beta[tid];
    if (tid < 64) { sSum[tid] = 0.f; sSum2[tid] = 0.f; }
    if (WRITE_Z) {
        sZ[tid] = 0.f;
        for (int i = tid; i < 512 * 8; i += 512) sW3[i] = W3[i];
    }

    // chunk loader: B (512 rows x 128B), A (64 rows x 128B)
    auto load_chunk = [&](int c, int sel) {
        const int kbase = c * 64;
        const uint32_t bB = sb + WS_B(sel);
#pragma unroll
        for (int i = tid; i < 4096; i += 512) {
            const int row = i >> 3, j = i & 7;
            cp16(bB + row * LDR + j * 16,
                 (const char*)W + ((size_t)row * KPAD + kbase) * 2 + j * 16);
        }
        {
            const int row = tid >> 3, j = tid & 7;    // 64 rows x 8 quads
            cp16(sb + WS_A(sel) + row * LDR + j * 16,
                 (const char*)A + (((size_t)tile * 64 + row) * KPAD + kbase) * 2 + j * 16);
        }
        CP_COMMIT();
    };

    load_chunk(0, 0);
    if (NC > 1) load_chunk(1, 1); else CP_COMMIT();

    float acc[2][8][4];
#pragma unroll
    for (int i = 0; i < 2; i++)
#pragma unroll
        for (int j = 0; j < 8; j++)
#pragma unroll
            for (int r = 0; r < 4; r++) acc[i][j][r] = 0.f;

    const int arow = ((lane >> 3) & 1) * 8 + (lane & 7);
    const int acol = (lane >> 4) * 8;
    const int brow = ((lane >> 4) & 1) * 8 + (lane & 7);
    const int bcol = ((lane >> 3) & 1) * 8;

#pragma unroll 1
    for (int c = 0; c < NC; c++) {
        if (c + 1 < NC) CP_WAIT(1); else CP_WAIT(0);
        __syncthreads();
        const int sel = c & 1;
        const uint32_t bA = sb + WS_A(sel);
        const uint32_t bB = sb + WS_B(sel);
#pragma unroll
        for (int ks = 0; ks < 64; ks += 16) {
            uint32_t ah[2][4];
#pragma unroll
            for (int mf = 0; mf < 2; mf++) {
                const uint32_t ao = (uint32_t)((warpM * 32 + mf * 16 + arow) * LDR
                                               + (ks + acol) * 2);
                LDSM4(ah[mf][0], ah[mf][1], ah[mf][2], ah[mf][3], bA + ao);
            }
#pragma unroll
            for (int nq = 0; nq < 4; nq++) {
                const uint32_t bo = (uint32_t)((nbase + nq * 16 + brow) * LDR
                                               + (ks + bcol) * 2);
                uint32_t b[4];
                LDSM4(b[0], b[1], b[2], b[3], bB + bo);
#pragma unroll
                for (int mf = 0; mf < 2; mf++) {
                    MMA16816(acc[mf][nq * 2],     ah[mf], b[0], b[1]);
                    MMA16816(acc[mf][nq * 2 + 1], ah[mf], b[2], b[3]);
                }
            }
        }
        __syncthreads();
        if (c + 2 < NC) load_chunk(c + 2, sel);
    }

    // ---------------- epilogue: bias -> LN stats ----------------------------
#pragma unroll
    for (int mf = 0; mf < 2; mf++)
#pragma unroll
        for (int rh = 0; rh < 2; rh++) {
            float s = 0.f, s2 = 0.f;
#pragma unroll
            for (int idx = 0; idx < 8; idx++) {
                const int c0 = nbase + idx * 8 + (lane & 3) * 2;
                float v0 = acc[mf][idx][rh * 2]     + sBias[c0];
                float v1 = acc[mf][idx][rh * 2 + 1] + sBias[c0 + 1];
                acc[mf][idx][rh * 2] = v0; acc[mf][idx][rh * 2 + 1] = v1;
                s += v0 + v1; s2 += v0 * v0 + v1 * v1;
            }
            s  += __shfl_xor_sync(0xffffffffu, s, 1);
            s  += __shfl_xor_sync(0xffffffffu, s, 2);
            s2 += __shfl_xor_sync(0xffffffffu, s2, 1);
            s2 += __shfl_xor_sync(0xffffffffu, s2, 2);
            if ((lane & 3) == 0) {
                const int row = warpM * 32 + mf * 16 + (lane >> 2) + rh * 8;
                atomicAdd(&sSum[row], s);
                atomicAdd(&sSum2[row], s2);
            }
        }
    __syncthreads();
    if (tid < 64) {
        const float mu = sSum[tid] * (1.f / 512.f);
        const float var = sSum2[tid] * (1.f / 512.f) - mu * mu;
        sMu[tid] = mu; sRs[tid] = rsqrtf(var + 1e-5f);
    }
    __syncthreads();

    // ---------------- LN + SiLU, store fp16 or fused z = tanh(h@W3+b3) ------
#pragma unroll
    for (int mf = 0; mf < 2; mf++)
#pragma unroll
        for (int rh = 0; rh < 2; rh++) {
            const int row = warpM * 32 + mf * 16 + (lane >> 2) + rh * 8;
            const float mu = sMu[row], rs = sRs[row];
            float zp[8];
            if (WRITE_Z) {
#pragma unroll
                for (int j = 0; j < 8; j++) zp[j] = 0.f;
            }
            const size_t rowg = (size_t)tile * 64 + row;
#pragma unroll
            for (int idx = 0; idx < 8; idx++) {
                const int c0 = nbase + idx * 8 + (lane & 3) * 2;
                float y0 = (acc[mf][idx][rh * 2]     - mu) * rs * sG[c0]     + sBe[c0];
                float y1 = (acc[mf][idx][rh * 2 + 1] - mu) * rs * sG[c0 + 1] + sBe[c0 + 1];
                y0 = y0 * (1.f / (1.f + __expf(-y0)));
                y1 = y1 * (1.f / (1.f + __expf(-y1)));
                if (WRITE_Z) {
                    const float* w0 = sW3 + c0 * 8;
#pragma unroll
                    for (int j = 0; j < 8; j++) {
                        zp[j] = fmaf(y0, w0[j], zp[j]);
                        zp[j] = fmaf(y1, w0[8 + j], zp[j]);
                    }
                } else {
                    *(uint32_t*)(O + rowg * 512 + c0) = pack_h2(y0, y1);
                }
            }
            if (WRITE_Z) {
#pragma unroll
                for (int j = 0; j < 8; j++) {
                    zp[j] += __shfl_xor_sync(0xffffffffu, zp[j], 1);
                    zp[j] += __shfl_xor_sync(0xffffffffu, zp[j], 2);
                }
                if ((lane & 3) == 0)
#pragma unroll
                    for (int j = 0; j < 8; j++)
                        atomicAdd(&sZ[row * 8 + j], zp[j]);
            }
        }

    if (WRITE_Z) {
        __syncthreads();
        if (tid < 64) {
            const size_t rowg = (size_t)tile * 64 + tid;
#pragma unroll
            for (int j = 0; j < 8; j++)
                z0out[rowg * 8 + j] = tanhf(sZ[tid * 8 + j] + __ldg(b3 + j));
        }
    }
}

// ============================================================================
// out layer: out[B,64] = A[B,512] @ W3 + b3 (fp32 out, no LN).
// CTA: M=128, N=64. 256 thr = 8 warps (4Mx2N), warp m32 x n32. BK=64,
// 2-stage, 2 CTAs/SM.
// ============================================================================
#define OST      27648
#define OS_A(s)  ((s) * OST)                    // 128*144 = 18432
#define OS_B(s)  ((s) * OST + 18432)            // 64*144  = 9216
#define SM_OUT   55296

__global__ __launch_bounds__(256, 2)
void out_mma_kernel(const __half* __restrict__ A,
                    const __half* __restrict__ W,
                    const float* __restrict__ bias,
                    float* __restrict__ out)
{
    constexpr int NC = 8;
    extern __shared__ char smem[];
    const uint32_t sb = smem_u32(smem);
    const int tid = threadIdx.x, lane = tid & 31, w = tid >> 5;
    const int warpM = w >> 1, warpN = w & 1;
    const int nbase = warpN * 32;
    const int tile = blockIdx.x;

    auto load_chunk = [&](int c, int sel) {
        const int kbase = c * 64;
#pragma unroll
        for (int i = tid; i < 512; i += 256) {       // 64 rows x 8 quads
            const int row = i >> 3, j = i & 7;
            cp16(sb + OS_B(sel) + row * LDR + j * 16,
                 (const char*)W + ((size_t)row * 512 + kbase) * 2 + j * 16);
        }
#pragma unroll
        for (int i = tid; i < 1024; i += 256) {      // 128 rows x 8 quads
            const int row = i >> 3, j = i & 7;
            cp16(sb + OS_A(sel) + row * LDR + j * 16,
                 (const char*)A + (((size_t)tile * 128 + row) * 512 + kbase) * 2 + j * 16);
        }
        CP_COMMIT();
    };

    load_chunk(0, 0);
    load_chunk(1, 1);

    float acc[2][4][4];
#pragma unroll
    for (int i = 0; i < 2; i++)
#pragma unroll
        for (int j = 0; j < 4; j++)
#pragma unroll
            for (int r = 0; r < 4; r++) acc[i][j][r] = 0.f;

    const int arow = ((lane >> 3) & 1) * 8 + (lane & 7);
    const int acol = (lane >> 4) * 8;
    const int brow = ((lane >> 4) & 1) * 8 + (lane & 7);
    const int bcol = ((lane >> 3) & 1) * 8;

#pragma unroll 1
    for (int c = 0; c < NC; c++) {
        if (c + 1 < NC) CP_WAIT(1); else CP_WAIT(0);
        __syncthreads();
        const int sel = c & 1;
        const uint32_t bA = sb + OS_A(sel);
        const uint32_t bB = sb + OS_B(sel);
#pragma unroll
        for (int ks = 0; ks < 64; ks += 16) {
            uint32_t ah[2][4];
#pragma unroll
            for (int mf = 0; mf < 2; mf++) {
                const uint32_t ao = (uint32_t)((warpM * 32 + mf * 16 + arow) * LDR
                                               + (ks + acol) * 2);
                LDSM4(ah[mf][0], ah[mf][1], ah[mf][2], ah[mf][3], bA + ao);
            }
#pragma unroll
            for (int nq = 0; nq < 2; nq++) {
                const uint32_t bo = (uint32_t)((nbase + nq * 16 + brow) * LDR
                                               + (ks + bcol) * 2);
                uint32_t b[4];
                LDSM4(b[0], b[1], b[2], b[3], bB + bo);
#pragma unroll
                for (int mf = 0; mf < 2; mf++) {
                    MMA16816(acc[mf][nq * 2],     ah[mf], b[0], b[1]);
                    MMA16816(acc[mf][nq * 2 + 1], ah[mf], b[2], b[3]);
                }
            }
        }
        __syncthreads();
        if (c + 2 < NC) load_chunk(c + 2, sel);
    }

#pragma unroll
    for (int mf = 0; mf < 2; mf++)
#pragma unroll
        for (int rh = 0; rh < 2; rh++) {
            const int row = warpM * 32 + mf * 16 + (lane >> 2) + rh * 8;
            const size_t rowg = (size_t)tile * 128 + row;
#pragma unroll
            for (int idx = 0; idx < 4; idx++) {
                const int c0 = nbase + idx * 8 + (lane & 3) * 2;
                float2 o;
                o.x = acc[mf][idx][rh * 2]     + __ldg(bias + c0);
                o.y = acc[mf][idx][rh * 2 + 1] + __ldg(bias + c0 + 1);
                *(float2*)(out + rowg * 64 + c0) = o;
            }
        }
}

// ============================================================================
// integrator: 20 Euler steps; outputs fp16 row-major padded to 64 cols
// ============================================================================
__global__ __launch_bounds__(256, 4)
void integrate_kernel(const float* __restrict__ z0,
                      const float* __restrict__ dtv,
                      const float* __restrict__ Xi,
                      __half* __restrict__ Z)
{
    __shared__ float Xis[NTH * LDIM];
    for (int i = threadIdx.x; i < NTH * LDIM; i += 256) Xis[i] = Xi[i];
    __syncthreads();

    const size_t row = (size_t)blockIdx.x * 256 + threadIdx.x;
    float z[8];
    *(float4*)&z[0] = *(const float4*)(z0 + row * 8);
    *(float4*)&z[4] = *(const float4*)(z0 + row * 8 + 4);
    const float dt = dtv[row] * (1.f / (float)NSTEPS);

#pragma unroll 1
    for (int s = 0; s < NSTEPS; s++) {
        float zd[8];
#pragma unroll
        for (int j = 0; j < 8; j++) zd[j] = Xis[j];
#pragma unroll
        for (int i = 0; i < 8; i++) {
            const float t = z[i];
#pragma unroll
            for (int j = 0; j < 8; j++)
                zd[j] = fmaf(t, Xis[(1 + i) * 8 + j], zd[j]);
        }
        int idx = 9;
#pragma unroll
        for (int i = 0; i < 8; i++)
#pragma unroll
            for (int k = i; k < 8; k++) {
                const float q = z[i] * z[k];
#pragma unroll
                for (int j = 0; j < 8; j++)
                    zd[j] = fmaf(q, Xis[idx * 8 + j], zd[j]);
                idx++;
            }
#pragma unroll
        for (int j = 0; j < 8; j++) z[j] = fmaf(zd[j], dt, z[j]);
    }

    uint4 qh, qz;
    qh.x = pack_h2(z[0], z[1]); qh.y = pack_h2(z[2], z[3]);
    qh.z = pack_h2(z[4], z[5]); qh.w = pack_h2(z[6], z[7]);
    qz.x = qz.y = qz.z = qz.w = 0u;
    uint4* ph = (uint4*)(Z + row * 64);
    ph[0] = qh;
#pragma unroll
    for (int u = 1; u < 8; u++) ph[u] = qz;
}

// ============================================================================
extern "C" void kernel_launch(void* const* d_in, const int* in_sizes, int n_in,
                              void* d_out, int out_size)
{
    (void)in_sizes; (void)n_in; (void)out_size;
    const float* x0   = (const float*)d_in[0];
    const float* dtn  = (const float*)d_in[1];
    const float* eW1  = (const float*)d_in[4];
    const float* eb1  = (const float*)d_in[5];
    const float* eg1  = (const float*)d_in[6];
    const float* ebe1 = (const float*)d_in[7];
    const float* eW2  = (const float*)d_in[8];
    const float* eb2  = (const float*)d_in[9];
    const float* eg2  = (const float*)d_in[10];
    const float* ebe2 = (const float*)d_in[11];
    const float* eW3  = (const float*)d_in[12];
    const float* eb3  = (const float*)d_in[13];
    const float* dW1  = (const float*)d_in[14];
    const float* db1  = (const float*)d_in[15];
    const float* dg1  = (const float*)d_in[16];
    const float* dbe1 = (const float*)d_in[17];
    const float* dW2  = (const float*)d_in[18];
    const float* db2  = (const float*)d_in[19];
    const float* dg2  = (const float*)d_in[20];
    const float* dbe2 = (const float*)d_in[21];
    const float* dW3  = (const float*)d_in[22];
    const float* db3  = (const float*)d_in[23];
    const float* Xi   = (const float*)d_in[24];
    float* out = (float*)d_out;

    __half *hA, *hB, *xh, *zh;
    __half *w1, *w2, *d1, *d2, *d3;
    float* z0;
    cudaGetSymbolAddress((void**)&hA, g_hA);
    cudaGetSymbolAddress((void**)&hB, g_hB);
    cudaGetSymbolAddress((void**)&xh, g_x);
    cudaGetSymbolAddress((void**)&zh, g_z);
    cudaGetSymbolAddress((void**)&z0, g_z0);
    cudaGetSymbolAddress((void**)&w1, g_w1);
    cudaGetSymbolAddress((void**)&w2, g_w2);
    cudaGetSymbolAddress((void**)&d1, g_d1);
    cudaGetSymbolAddress((void**)&d2, g_d2);
    cudaGetSymbolAddress((void**)&d3, g_d3);

    cudaFuncSetAttribute(wide_mma_kernel<64, false>,
        cudaFuncAttributeMaxDynamicSharedMemorySize, SM_WIDE);
    cudaFuncSetAttribute(wide_mma_kernel<512, false>,
        cudaFuncAttributeMaxDynamicSharedMemorySize, SM_WIDE);
    cudaFuncSetAttribute(wide_mma_kernel<512, true>,
        cudaFuncAttributeMaxDynamicSharedMemorySize, SM_WIDE);
    cudaFuncSetAttribute(out_mma_kernel,
        cudaFuncAttributeMaxDynamicSharedMemorySize, SM_OUT);

    // ---- prep: single launch for all weights, one for x ----
    prep_all_kernel<<<(SEG4 + 255) / 256, 256>>>(eW1, eW2, dW1, dW2, dW3,
                                                 w1, w2, d1, d2, d3);
    prep_x_kernel<<<(BATCH * 64) / 256, 256>>>(x0, xh);

    const int nwide = BATCH / 64;    // 2048

    // ---- pipeline ----
    wide_mma_kernel<64, false><<<nwide, 512, SM_WIDE>>>(
        xh, w1, eb1, eg1, ebe1, hA, nullptr, nullptr, nullptr);
    wide_mma_kernel<512, true><<<nwide, 512, SM_WIDE>>>(
        hA, w2, eb2, eg2, ebe2, nullptr, eW3, eb3, z0);
    integrate_kernel<<<BATCH / 256, 256>>>(z0, dtn, Xi, zh);
    wide_mma_kernel<64, false><<<nwide, 512, SM_WIDE>>>(
        zh, d1, db1, dg1, dbe1, hA, nullptr, nullptr, nullptr);
    wide_mma_kernel<512, false><<<nwide, 512, SM_WIDE>>>(
        hA, d2, db2, dg2, dbe2, hB, nullptr, nullptr, nullptr);
    out_mma_kernel<<<BATCH / 128, 256, SM_OUT>>>(hB, d3, db3, out);
}